// round 4
// baseline (speedup 1.0000x reference)
#include <cuda_runtime.h>

// VQ-VAE forward — fp32 with bitwise emulation of XLA-CPU reference numerics.
// Key: dist = fl( fl(zsq_n + esq_k) - 2*g_nk ), all reductions sequential
// ascending (Eigen-style FMA chains for GEMMs, separate mul+add for norms),
// argmin with lowest-index tie-break.

#define N_PIX 32768
#define D_DIM 256
#define K_CB  4096

// ---- scratch (static device globals; no allocation) ----
__device__ float g_z[N_PIX * D_DIM];          // 32 MB: pre-VQ activations [n][d]
__device__ float g_wt[D_DIM * D_DIM];         // transposed conv weights wt[c][d]
__device__ float g_esq[K_CB];                 // ||e_k||^2 (sequential order)
__device__ float g_zsq[N_PIX];                // ||z_n||^2 (sequential order)
__device__ int   g_idx[N_PIX];                // argmin code per pixel
__device__ unsigned int g_counts[K_CB];       // code histogram
__device__ float g_loss;                      // sum of (q-z)^2

// ============================================================
// prep: transpose W for coalesced conv, zero counts/loss
// ============================================================
__global__ void prep_kernel(const float* __restrict__ conv_w) {
    int gid = blockIdx.x * 256 + threadIdx.x;
    if (gid < D_DIM * D_DIM) {
        int c = gid >> 8, d = gid & 255;
        g_wt[gid] = conv_w[d * D_DIM + c];   // wt[c][d] = W[d][c]
    }
    if (gid < K_CB) g_counts[gid] = 0u;
    if (gid == 0) g_loss = 0.f;
}

// ============================================================
// esq: ||e_k||^2, STRICT sequential d ascending, mul and add each
// rounded separately (emulates XLA-CPU fused elementwise+reduce loop).
// ============================================================
__global__ void esq_kernel(const float* __restrict__ emb) {
    int k = blockIdx.x * 256 + threadIdx.x;
    if (k >= K_CB) return;
    const float* er = emb + (size_t)k * D_DIM;
    float s = 0.f;
    #pragma unroll 8
    for (int d = 0; d < D_DIM; d++)
        s = __fadd_rn(s, __fmul_rn(er[d], er[d]));
    g_esq[k] = s;
}

// ============================================================
// conv: z[n][d] = fl( chain_{c=0..255} fma(x[n,c], W[d,c]) + b[d] )
// Eigen gebp semantics: single accumulator, ascending c, fused FMA,
// bias added once at the end (separate XLA add op).
// ============================================================
__global__ __launch_bounds__(256) void conv_kernel(const float* __restrict__ x,
                                                   const float* __restrict__ conv_b) {
    __shared__ float xs[D_DIM * 32];   // xs[c][w], 32 KB
    int t = threadIdx.x;
    int n0 = blockIdx.x * 32;
    int b = n0 >> 10, h = (n0 >> 5) & 31;
    const float* xb = x + (size_t)b * (D_DIM * 1024) + h * 32;

    int lane = t & 31, cg = t >> 5;
    #pragma unroll 4
    for (int i = 0; i < 32; i++) {
        int c = cg * 32 + i;
        xs[c * 32 + lane] = xb[c * 1024 + lane];   // coalesced
    }
    __syncthreads();

    int d = t;
    float4 acc[8];
    #pragma unroll
    for (int p = 0; p < 8; p++) acc[p] = make_float4(0.f, 0.f, 0.f, 0.f);
    const float4* xs4 = (const float4*)xs;

    for (int c0 = 0; c0 < D_DIM; c0 += 8) {
        float w[8];
        #pragma unroll
        for (int cc = 0; cc < 8; cc++) w[cc] = g_wt[(c0 + cc) * D_DIM + d];
        #pragma unroll
        for (int p4 = 0; p4 < 8; p4++) {
            #pragma unroll
            for (int cc = 0; cc < 8; cc++) {   // ascending c chain per output
                float4 xv = xs4[(c0 + cc) * 8 + p4];
                acc[p4].x = __fmaf_rn(xv.x, w[cc], acc[p4].x);
                acc[p4].y = __fmaf_rn(xv.y, w[cc], acc[p4].y);
                acc[p4].z = __fmaf_rn(xv.z, w[cc], acc[p4].z);
                acc[p4].w = __fmaf_rn(xv.w, w[cc], acc[p4].w);
            }
        }
    }
    float cb = conv_b[d];
    #pragma unroll
    for (int p4 = 0; p4 < 8; p4++) {
        g_z[(size_t)(n0 + p4 * 4 + 0) * D_DIM + d] = __fadd_rn(acc[p4].x, cb);
        g_z[(size_t)(n0 + p4 * 4 + 1) * D_DIM + d] = __fadd_rn(acc[p4].y, cb);
        g_z[(size_t)(n0 + p4 * 4 + 2) * D_DIM + d] = __fadd_rn(acc[p4].z, cb);
        g_z[(size_t)(n0 + p4 * 4 + 3) * D_DIM + d] = __fadd_rn(acc[p4].w, cb);
    }
}

// ============================================================
// zsq: ||z_n||^2, strict sequential d ascending, separate mul+add.
// ============================================================
__global__ void zsq_kernel() {
    int n = blockIdx.x * 256 + threadIdx.x;
    if (n >= N_PIX) return;
    const float* zr = g_z + (size_t)n * D_DIM;
    float s = 0.f;
    #pragma unroll 8
    for (int d = 0; d < D_DIM; d++)
        s = __fadd_rn(s, __fmul_rn(zr[d], zr[d]));
    g_zsq[n] = s;
}

// ============================================================
// dist+argmin: per pixel n,  dist = fl( fl(zsq_n + esq_k) - 2*g_nk ),
// g_nk = ascending-d FMA chain (matches Eigen). Running min as packed
// u64 (orderable float hi, index lo) -> exact lowest-index tie-break.
// CTA = 128 pixels x 128-code tiles, 256 thr, 8x8 strided micro-tile.
// ============================================================
__global__ __launch_bounds__(256, 2) void dist_kernel(const float* __restrict__ emb) {
    __shared__ float zs[32][129];      // [d][row], conflict-free
    __shared__ float es[32][129];      // [d][code]
    __shared__ float esq_s[128];
    __shared__ float zsq_s[128];

    int t = threadIdx.x;
    int tx = t & 15, ty = t >> 4;
    int n0 = blockIdx.x * 128;

    if (t < 128) zsq_s[t] = g_zsq[n0 + t];

    unsigned long long best[8];
    #pragma unroll
    for (int i = 0; i < 8; i++) best[i] = 0xFFFFFFFFFFFFFFFFull;

    for (int kt = 0; kt < 32; kt++) {
        __syncthreads();                       // prev scoring done with esq_s
        if (t < 128) esq_s[t] = g_esq[kt * 128 + t];

        float acc[8][8];
        #pragma unroll
        for (int i = 0; i < 8; i++)
            #pragma unroll
            for (int j = 0; j < 8; j++) acc[i][j] = 0.f;

        for (int dc = 0; dc < 8; dc++) {       // ascending d chunks
            __syncthreads();
            #pragma unroll
            for (int l = 0; l < 4; l++) {
                int idx = t + 256 * l;
                int r = idx >> 3, f4 = idx & 7;
                float4 zv = ((const float4*)g_z)[(size_t)(n0 + r) * 64 + dc * 8 + f4];
                zs[f4 * 4 + 0][r] = zv.x; zs[f4 * 4 + 1][r] = zv.y;
                zs[f4 * 4 + 2][r] = zv.z; zs[f4 * 4 + 3][r] = zv.w;
                float4 ev = ((const float4*)emb)[(size_t)(kt * 128 + r) * 64 + dc * 8 + f4];
                es[f4 * 4 + 0][r] = ev.x; es[f4 * 4 + 1][r] = ev.y;
                es[f4 * 4 + 2][r] = ev.z; es[f4 * 4 + 3][r] = ev.w;
            }
            __syncthreads();
            #pragma unroll 4
            for (int d = 0; d < 32; d++) {     // ascending d within chunk
                float zf[8], ef[8];
                #pragma unroll
                for (int i = 0; i < 8; i++) zf[i] = zs[d][ty + 16 * i];
                #pragma unroll
                for (int j = 0; j < 8; j++) ef[j] = es[d][tx + 16 * j];
                #pragma unroll
                for (int i = 0; i < 8; i++)
                    #pragma unroll
                    for (int j = 0; j < 8; j++)
                        acc[i][j] = __fmaf_rn(zf[i], ef[j], acc[i][j]);
            }
        }
        // ref scoring: dist = fl( fl(zsq + esq) - 2*g )   (2*g exact)
        #pragma unroll
        for (int j = 0; j < 8; j++) {
            float eq = esq_s[tx + 16 * j];
            unsigned int kk = (unsigned int)(kt * 128 + tx + 16 * j);
            #pragma unroll
            for (int i = 0; i < 8; i++) {
                float C = __fadd_rn(zsq_s[ty + 16 * i], eq);
                float s = __fadd_rn(C, -2.f * acc[i][j]);
                unsigned int u = __float_as_uint(s);
                u = (u & 0x80000000u) ? ~u : (u | 0x80000000u);
                unsigned long long key = ((unsigned long long)u << 32) | kk;
                if (key < best[i]) best[i] = key;
            }
        }
    }

    // reduce over the 16 tx lanes sharing each row (within half-warp)
    #pragma unroll
    for (int i = 0; i < 8; i++) {
        unsigned long long b0 = best[i];
        #pragma unroll
        for (int off = 8; off; off >>= 1) {
            unsigned long long o = __shfl_xor_sync(0xffffffffu, b0, off, 16);
            if (o < b0) b0 = o;
        }
        if (tx == 0) g_idx[n0 + ty + 16 * i] = (int)(b0 & 0xFFFFFFFFu);
    }
}

// ============================================================
// epilogue: out[b,d,h,w] = fl(z + fl(q - z))  (exact ref fp order)
// loss partial sums, code histogram. block = one (b,h) row (32 pixels).
// ============================================================
__global__ __launch_bounds__(256) void epilogue_kernel(const float* __restrict__ emb,
                                                       float* __restrict__ out) {
    __shared__ float st_s[D_DIM * 33];    // [d][w] padded
    __shared__ int idx_s[32];
    __shared__ float wsum[8];
    int t = threadIdx.x;
    int bh = blockIdx.x;
    int b = bh >> 5, h = bh & 31;
    int n0 = bh * 32;

    if (t < 32) idx_s[t] = g_idx[n0 + t];
    __syncthreads();

    float lsum = 0.f;
    for (int p = 0; p < 32; p++) {
        float zv = g_z[(size_t)(n0 + p) * D_DIM + t];
        float qv = emb[(size_t)idx_s[p] * D_DIM + t];
        float diff = __fadd_rn(qv, -zv);
        lsum += diff * diff;
        st_s[t * 33 + p] = __fadd_rn(zv, diff);   // == ref z + (q - z)
    }
    __syncthreads();

    int w = t & 31, dg = t >> 5;
    float* ob = out + (size_t)b * (D_DIM * 1024) + h * 32;
    #pragma unroll 4
    for (int dd = 0; dd < 32; dd++) {
        int d = dg * 32 + dd;
        ob[(size_t)d * 1024 + w] = st_s[d * 33 + w];   // coalesced
    }

    #pragma unroll
    for (int off = 16; off; off >>= 1) lsum += __shfl_xor_sync(0xffffffffu, lsum, off);
    if ((t & 31) == 0) wsum[t >> 5] = lsum;
    __syncthreads();
    if (t == 0) {
        float s = 0.f;
        #pragma unroll
        for (int i = 0; i < 8; i++) s += wsum[i];
        atomicAdd(&g_loss, s);
    }
    if (t < 32) atomicAdd(&g_counts[idx_s[t]], 1u);
}

// ============================================================
// finalize: loss = 1.25 * mean((q-z)^2); perplexity from histogram
// (count/32768 is exact; 1.25*m == m + 0.25*m bitwise)
// ============================================================
__global__ void finalize_kernel(float* __restrict__ out, int out_size) {
    __shared__ float red[512];
    int t = threadIdx.x;
    float s = 0.f;
    for (int k = t; k < K_CB; k += 512) {
        float avg = (float)g_counts[k] / (float)N_PIX;
        s += avg * logf(avg + 1e-10f);
    }
    red[t] = s;
    __syncthreads();
    for (int o = 256; o; o >>= 1) {
        if (t < o) red[t] += red[t + o];
        __syncthreads();
    }
    if (t == 0) {
        out[out_size - 2] = 1.25f * (g_loss / (float)(N_PIX * D_DIM));
        out[out_size - 1] = expf(-red[0]);
    }
}

extern "C" void kernel_launch(void* const* d_in, const int* in_sizes, int n_in,
                              void* d_out, int out_size) {
    const float* x      = (const float*)d_in[0];
    const float* conv_w = (const float*)d_in[1];
    const float* conv_b = (const float*)d_in[2];
    const float* emb    = (const float*)d_in[3];
    float* out = (float*)d_out;

    prep_kernel<<<257, 256>>>(conv_w);
    esq_kernel<<<16, 256>>>(emb);
    conv_kernel<<<N_PIX / 32, 256>>>(x, conv_b);
    zsq_kernel<<<N_PIX / 256, 256>>>();
    dist_kernel<<<N_PIX / 128, 256>>>(emb);
    epilogue_kernel<<<N_PIX / 32, 256>>>(emb, out);
    finalize_kernel<<<1, 512>>>(out, out_size);
}

// round 5
// speedup vs baseline: 2.0275x; 2.0275x over previous
#include <cuda_runtime.h>

// VQ-VAE forward — tf32 tensor-core candidate filter + exact fp32 rescore.
// Exact numerics (XLA-CPU sequential chains) preserved for all outputs.

#define N_PIX 32768
#define D_DIM 256
#define K_CB  4096
#define CAP   64
#define MARGIN 4e-4f
#define EB_STRIDE 68   // 64 dims + 4 pad (bank-conflict-free B-frag loads)

// ---- scratch (static device globals; no allocation) ----
__device__ float g_z[N_PIX * D_DIM];          // 32 MB pre-VQ activations [n][d]
__device__ float g_wt[D_DIM * D_DIM];         // transposed conv weights
__device__ float g_esq[K_CB];                 // ||e_k||^2 (sequential chain)
__device__ float g_zsq[N_PIX];                // ||z_n||^2 (sequential chain)
__device__ int   g_idx[N_PIX];
__device__ unsigned int g_counts[K_CB];
__device__ float g_loss;
__device__ unsigned short g_cand[N_PIX * CAP]; // candidate code ids
__device__ int g_ccnt[N_PIX];                  // candidate counts

__device__ __forceinline__ void cp16(void* dst, const void* src) {
    unsigned d = (unsigned)__cvta_generic_to_shared(dst);
    asm volatile("cp.async.cg.shared.global [%0], [%1], 16;\n" :: "r"(d), "l"(src));
}

// ============================================================
// prep: transpose W, zero counts/loss
// ============================================================
__global__ void prep_kernel(const float* __restrict__ conv_w) {
    int gid = blockIdx.x * 256 + threadIdx.x;
    if (gid < D_DIM * D_DIM) {
        int c = gid >> 8, d = gid & 255;
        g_wt[gid] = conv_w[d * D_DIM + c];
    }
    if (gid < K_CB) g_counts[gid] = 0u;
    if (gid == 0) g_loss = 0.f;
}

// ============================================================
// esq: strict sequential ascending-d, separate mul+add
// ============================================================
__global__ void esq_kernel(const float* __restrict__ emb) {
    int k = blockIdx.x * 256 + threadIdx.x;
    if (k >= K_CB) return;
    const float4* er = (const float4*)(emb + (size_t)k * D_DIM);
    float s = 0.f;
    #pragma unroll 16
    for (int i = 0; i < 64; i++) {
        float4 v = er[i];
        s = __fadd_rn(s, __fmul_rn(v.x, v.x));
        s = __fadd_rn(s, __fmul_rn(v.y, v.y));
        s = __fadd_rn(s, __fmul_rn(v.z, v.z));
        s = __fadd_rn(s, __fmul_rn(v.w, v.w));
    }
    g_esq[k] = s;
}

// ============================================================
// conv: Eigen-order ascending-c FMA chain, bias added last
// ============================================================
__global__ __launch_bounds__(256) void conv_kernel(const float* __restrict__ x,
                                                   const float* __restrict__ conv_b) {
    __shared__ float xs[D_DIM * 32];
    int t = threadIdx.x;
    int n0 = blockIdx.x * 32;
    int b = n0 >> 10, h = (n0 >> 5) & 31;
    const float* xb = x + (size_t)b * (D_DIM * 1024) + h * 32;

    int lane = t & 31, cg = t >> 5;
    #pragma unroll 4
    for (int i = 0; i < 32; i++) {
        int c = cg * 32 + i;
        xs[c * 32 + lane] = xb[c * 1024 + lane];
    }
    __syncthreads();

    int d = t;
    float4 acc[8];
    #pragma unroll
    for (int p = 0; p < 8; p++) acc[p] = make_float4(0.f, 0.f, 0.f, 0.f);
    const float4* xs4 = (const float4*)xs;

    for (int c0 = 0; c0 < D_DIM; c0 += 8) {
        float w[8];
        #pragma unroll
        for (int cc = 0; cc < 8; cc++) w[cc] = g_wt[(c0 + cc) * D_DIM + d];
        #pragma unroll
        for (int p4 = 0; p4 < 8; p4++) {
            #pragma unroll
            for (int cc = 0; cc < 8; cc++) {
                float4 xv = xs4[(c0 + cc) * 8 + p4];
                acc[p4].x = __fmaf_rn(xv.x, w[cc], acc[p4].x);
                acc[p4].y = __fmaf_rn(xv.y, w[cc], acc[p4].y);
                acc[p4].z = __fmaf_rn(xv.z, w[cc], acc[p4].z);
                acc[p4].w = __fmaf_rn(xv.w, w[cc], acc[p4].w);
            }
        }
    }
    float cb = conv_b[d];
    #pragma unroll
    for (int p4 = 0; p4 < 8; p4++) {
        g_z[(size_t)(n0 + p4 * 4 + 0) * D_DIM + d] = __fadd_rn(acc[p4].x, cb);
        g_z[(size_t)(n0 + p4 * 4 + 1) * D_DIM + d] = __fadd_rn(acc[p4].y, cb);
        g_z[(size_t)(n0 + p4 * 4 + 2) * D_DIM + d] = __fadd_rn(acc[p4].z, cb);
        g_z[(size_t)(n0 + p4 * 4 + 3) * D_DIM + d] = __fadd_rn(acc[p4].w, cb);
    }
}

// ============================================================
// zsq: strict sequential ascending-d chain (float4 loads)
// ============================================================
__global__ void zsq_kernel() {
    int n = blockIdx.x * 256 + threadIdx.x;
    const float4* zr = (const float4*)(g_z + (size_t)n * D_DIM);
    float s = 0.f;
    #pragma unroll 16
    for (int i = 0; i < 64; i++) {
        float4 v = zr[i];
        s = __fadd_rn(s, __fmul_rn(v.x, v.x));
        s = __fadd_rn(s, __fmul_rn(v.y, v.y));
        s = __fadd_rn(s, __fmul_rn(v.z, v.z));
        s = __fadd_rn(s, __fmul_rn(v.w, v.w));
    }
    g_zsq[n] = s;
}

// ============================================================
// dist_mma: tf32 mma.sync GEMM, per-pixel shared running min,
// candidate push within MARGIN. CTA = 128 pixels; loops 32
// code-tiles of 128; Z tile resident in smem (frag-packed),
// E staged per 64-dim chunk via 2-stage cp.async pipeline.
// smem floats: zA[32768] | eB[2*128*68] | zsq[128] esq[128]
//              minv[128] | cnt[128] | cand[128*64 u16]
// ============================================================
__global__ void __launch_bounds__(256, 1) dist_mma_kernel(const float* __restrict__ emb) {
    extern __shared__ char smem[];
    float* zA    = (float*)smem;                            // 131072 B
    float* eB    = (float*)(smem + 131072);                 // 69632 B
    float* zsq_s = (float*)(smem + 131072 + 69632);         // 512 B
    float* esq_s = zsq_s + 128;
    float* minv  = esq_s + 128;
    int*   cnt_s = (int*)(minv + 128);
    unsigned short* cand_s = (unsigned short*)(cnt_s + 128); // 16384 B

    int t = threadIdx.x;
    int lane = t & 31, warp = t >> 5;
    int wm = warp >> 2, wn = warp & 3;         // 2 x 4 warp grid
    int g = lane >> 2, q = lane & 3;
    int n0 = blockIdx.x * 128;

    if (t < 128) { zsq_s[t] = g_zsq[n0 + t]; minv[t] = 3.0e38f; cnt_s[t] = 0; }

    // stage Z tile into A-fragment-packed layout (raw fp32 bits; HW uses tf32 subset)
    #pragma unroll 4
    for (int l = 0; l < 32; l++) {
        int idx = t + 256 * l;                // 8192 float4s
        int r = idx >> 6, f4c = idx & 63;
        float4 v = ((const float4*)g_z)[(size_t)(n0 + r) * 64 + f4c];
        int mtile = r >> 4, rr = r & 15, gg = rr & 7, hi = rr >> 3;
        float vv[4] = {v.x, v.y, v.z, v.w};
        #pragma unroll
        for (int j = 0; j < 4; j++) {
            int d = f4c * 4 + j;
            int kstep = d >> 3, dd = d & 7, qq = dd & 3, khi = dd >> 2;
            int ln = gg * 4 + qq, comp = hi + 2 * khi;
            zA[(kstep * 8 + mtile) * 128 + ((ln * 4 + comp) ^ ((kstep & 7) * 4))] = vv[j];
        }
    }

    // prologue: issue stage 0 (kt=0, kc=0)
    {
        const float* src0 = emb;
        #pragma unroll
        for (int l = 0; l < 8; l++) {
            int idx = t + 256 * l;
            int crow = idx >> 4, seg = idx & 15;
            cp16(eB + crow * EB_STRIDE + seg * 4, src0 + (size_t)crow * 256 + seg * 4);
        }
        asm volatile("cp.async.commit_group;\n");
    }

    float acc[4][4][4];
    float lbest[8];
    #pragma unroll
    for (int i = 0; i < 8; i++) lbest[i] = 3.0e38f;

    #pragma unroll 1
    for (int s = 0; s < 128; s++) {
        int kc = s & 3, buf = s & 1, kt = s >> 2;
        if (s + 1 < 128) {
            int kt1 = (s + 1) >> 2, kc1 = (s + 1) & 3, buf1 = (s + 1) & 1;
            float* dbase = eB + buf1 * (128 * EB_STRIDE);
            const float* src0 = emb + (size_t)(kt1 * 128) * 256 + kc1 * 64;
            #pragma unroll
            for (int l = 0; l < 8; l++) {
                int idx = t + 256 * l;
                int crow = idx >> 4, seg = idx & 15;
                cp16(dbase + crow * EB_STRIDE + seg * 4, src0 + (size_t)crow * 256 + seg * 4);
            }
            asm volatile("cp.async.commit_group;\n");
            asm volatile("cp.async.wait_group 1;\n");
        } else {
            asm volatile("cp.async.wait_group 0;\n");
        }
        __syncthreads();

        if (kc == 0) {
            if (t < 128) esq_s[t] = g_esq[kt * 128 + t];
            #pragma unroll
            for (int mi = 0; mi < 4; mi++)
                #pragma unroll
                for (int ni = 0; ni < 4; ni++)
                    #pragma unroll
                    for (int c = 0; c < 4; c++) acc[mi][ni][c] = 0.f;
        }

        float* ebuf = eB + buf * (128 * EB_STRIDE);
        #pragma unroll
        for (int ks = 0; ks < 8; ks++) {
            int kg = kc * 8 + ks;
            unsigned a[4][4], bfr[4][2];
            #pragma unroll
            for (int mi = 0; mi < 4; mi++) {
                int mtile = wm * 4 + mi;
                float4 av = ((const float4*)zA)[(kg * 8 + mtile) * 32 + (lane ^ (kg & 7))];
                a[mi][0] = __float_as_uint(av.x); a[mi][1] = __float_as_uint(av.y);
                a[mi][2] = __float_as_uint(av.z); a[mi][3] = __float_as_uint(av.w);
            }
            #pragma unroll
            for (int ni = 0; ni < 4; ni++) {
                int cl = wn * 32 + ni * 8 + g;
                bfr[ni][0] = __float_as_uint(ebuf[cl * EB_STRIDE + ks * 8 + q]);
                bfr[ni][1] = __float_as_uint(ebuf[cl * EB_STRIDE + ks * 8 + q + 4]);
            }
            #pragma unroll
            for (int mi = 0; mi < 4; mi++)
                #pragma unroll
                for (int ni = 0; ni < 4; ni++)
                    asm volatile(
                        "mma.sync.aligned.m16n8k8.row.col.f32.tf32.tf32.f32 "
                        "{%0,%1,%2,%3}, {%4,%5,%6,%7}, {%8,%9}, {%0,%1,%2,%3};"
                        : "+f"(acc[mi][ni][0]), "+f"(acc[mi][ni][1]),
                          "+f"(acc[mi][ni][2]), "+f"(acc[mi][ni][3])
                        : "r"(a[mi][0]), "r"(a[mi][1]), "r"(a[mi][2]), "r"(a[mi][3]),
                          "r"(bfr[ni][0]), "r"(bfr[ni][1]));
        }

        if (kc == 3) {
            #pragma unroll
            for (int mi = 0; mi < 4; mi++) {
                #pragma unroll
                for (int hi = 0; hi < 2; hi++) {
                    int r = wm * 64 + mi * 16 + hi * 8 + g;
                    float zq = zsq_s[r];
                    int slot = mi * 2 + hi;
                    #pragma unroll
                    for (int ni = 0; ni < 4; ni++) {
                        #pragma unroll
                        for (int cc = 0; cc < 2; cc++) {
                            int col = wn * 32 + ni * 8 + 2 * q + cc;
                            float gv = acc[mi][ni][hi * 2 + cc];
                            float sv = __fadd_rn(__fadd_rn(zq, esq_s[col]), -2.f * gv);
                            if (sv < lbest[slot] + MARGIN) {
                                // rare path: consult/update shared min, maybe push
                                atomicMin((int*)&minv[r], __float_as_int(sv)); // dist > 0 always
                                float cm = minv[r];
                                if (sv < cm + MARGIN) {
                                    int pos = atomicAdd(&cnt_s[r], 1);
                                    if (pos < CAP)
                                        cand_s[r * CAP + pos] = (unsigned short)(kt * 128 + col);
                                }
                                if (sv < lbest[slot]) lbest[slot] = sv;
                            }
                        }
                    }
                }
            }
        }
        __syncthreads();
    }

    if (t < 128) g_ccnt[n0 + t] = cnt_s[t];
    for (int i = t; i < 128 * CAP; i += 256)
        g_cand[(size_t)n0 * CAP + i] = cand_s[i];
}

// ============================================================
// rescore: EXACT ascending-d FMA chain for candidates only;
// packed-u64 min => lowest-index tie-break. Warp per pixel.
// Overflowed pixels (> CAP cands): full 4096 exact scan.
// ============================================================
__global__ void __launch_bounds__(256) rescore_kernel(const float* __restrict__ emb) {
    __shared__ float zrow[8][256];
    int t = threadIdx.x, lane = t & 31, w = t >> 5;
    int n = blockIdx.x * 8 + w;

    #pragma unroll
    for (int l = 0; l < 2; l++) {
        int f4 = lane + 32 * l;
        ((float4*)zrow[w])[f4] = ((const float4*)g_z)[(size_t)n * 64 + f4];
    }
    __syncwarp();

    int cnt = g_ccnt[n];
    float zq = g_zsq[n];
    const float4* z4 = (const float4*)zrow[w];
    unsigned long long best = 0xFFFFFFFFFFFFFFFFull;

    int total = (cnt <= CAP) ? cnt : K_CB;
    for (int i = lane; i < total; i += 32) {
        int k = (cnt <= CAP) ? (int)g_cand[(size_t)n * CAP + i] : i;
        float a = 0.f;
        const float4* e4 = (const float4*)(emb + (size_t)k * D_DIM);
        #pragma unroll 8
        for (int d4 = 0; d4 < 64; d4++) {
            float4 ev = e4[d4], zv = z4[d4];
            a = __fmaf_rn(zv.x, ev.x, a);
            a = __fmaf_rn(zv.y, ev.y, a);
            a = __fmaf_rn(zv.z, ev.z, a);
            a = __fmaf_rn(zv.w, ev.w, a);
        }
        float s = __fadd_rn(__fadd_rn(zq, g_esq[k]), -2.f * a);
        unsigned u = __float_as_uint(s);
        u = (u & 0x80000000u) ? ~u : (u | 0x80000000u);
        unsigned long long key = ((unsigned long long)u << 32) | (unsigned)k;
        if (key < best) best = key;
    }
    #pragma unroll
    for (int off = 16; off; off >>= 1) {
        unsigned long long o = __shfl_xor_sync(0xffffffffu, best, off);
        if (o < best) best = o;
    }
    if (lane == 0) g_idx[n] = (int)(best & 0xFFFFFFFFu);
}

// ============================================================
// epilogue: out = fl(z + fl(q - z)); loss partials; histogram
// ============================================================
__global__ __launch_bounds__(256) void epilogue_kernel(const float* __restrict__ emb,
                                                       float* __restrict__ out) {
    __shared__ float st_s[D_DIM * 33];
    __shared__ int idx_s[32];
    __shared__ float wsum[8];
    int t = threadIdx.x;
    int bh = blockIdx.x;
    int b = bh >> 5, h = bh & 31;
    int n0 = bh * 32;

    if (t < 32) idx_s[t] = g_idx[n0 + t];
    __syncthreads();

    float lsum = 0.f;
    for (int p = 0; p < 32; p++) {
        float zv = g_z[(size_t)(n0 + p) * D_DIM + t];
        float qv = emb[(size_t)idx_s[p] * D_DIM + t];
        float diff = __fadd_rn(qv, -zv);
        lsum += diff * diff;
        st_s[t * 33 + p] = __fadd_rn(zv, diff);
    }
    __syncthreads();

    int w = t & 31, dg = t >> 5;
    float* ob = out + (size_t)b * (D_DIM * 1024) + h * 32;
    #pragma unroll 4
    for (int dd = 0; dd < 32; dd++) {
        int d = dg * 32 + dd;
        ob[(size_t)d * 1024 + w] = st_s[d * 33 + w];
    }

    #pragma unroll
    for (int off = 16; off; off >>= 1) lsum += __shfl_xor_sync(0xffffffffu, lsum, off);
    if ((t & 31) == 0) wsum[t >> 5] = lsum;
    __syncthreads();
    if (t == 0) {
        float s = 0.f;
        #pragma unroll
        for (int i = 0; i < 8; i++) s += wsum[i];
        atomicAdd(&g_loss, s);
    }
    if (t < 32) atomicAdd(&g_counts[idx_s[t]], 1u);
}

// ============================================================
// finalize
// ============================================================
__global__ void finalize_kernel(float* __restrict__ out, int out_size) {
    __shared__ float red[512];
    int t = threadIdx.x;
    float s = 0.f;
    for (int k = t; k < K_CB; k += 512) {
        float avg = (float)g_counts[k] / (float)N_PIX;
        s += avg * logf(avg + 1e-10f);
    }
    red[t] = s;
    __syncthreads();
    for (int o = 256; o; o >>= 1) {
        if (t < o) red[t] += red[t + o];
        __syncthreads();
    }
    if (t == 0) {
        out[out_size - 2] = 1.25f * (g_loss / (float)(N_PIX * D_DIM));
        out[out_size - 1] = expf(-red[0]);
    }
}

extern "C" void kernel_launch(void* const* d_in, const int* in_sizes, int n_in,
                              void* d_out, int out_size) {
    const float* x      = (const float*)d_in[0];
    const float* conv_w = (const float*)d_in[1];
    const float* conv_b = (const float*)d_in[2];
    const float* emb    = (const float*)d_in[3];
    float* out = (float*)d_out;

    const int DIST_SMEM = 131072 + 69632 + 4 * 512 + 16384;   // 219136 B
    cudaFuncSetAttribute(dist_mma_kernel,
                         cudaFuncAttributeMaxDynamicSharedMemorySize, DIST_SMEM);

    prep_kernel<<<257, 256>>>(conv_w);
    esq_kernel<<<16, 256>>>(emb);
    conv_kernel<<<N_PIX / 32, 256>>>(x, conv_b);
    zsq_kernel<<<N_PIX / 256, 256>>>();
    dist_mma_kernel<<<N_PIX / 128, 256, DIST_SMEM>>>(emb);
    rescore_kernel<<<N_PIX / 8, 256>>>(emb);
    epilogue_kernel<<<N_PIX / 32, 256>>>(emb, out);
    finalize_kernel<<<1, 512>>>(out, out_size);
}

// round 6
// speedup vs baseline: 2.5646x; 1.2649x over previous
#include <cuda_runtime.h>
#include <cuda_fp16.h>

// VQ-VAE forward — fp16 tensor-core candidate filter + exact fp32 rescore.
// Exact numerics (XLA-CPU sequential chains) preserved for all outputs.

#define N_PIX 32768
#define D_DIM 256
#define K_CB  4096
#define CAP   64
#define MARGIN 2.5e-4f

// ---- scratch (static device globals; no allocation) ----
__device__ float g_z[N_PIX * D_DIM];          // 32 MB pre-VQ activations [n][d]
__device__ __half g_zh[N_PIX * D_DIM];        // 16 MB fp16 copy (filter only)
__device__ __half g_eh[K_CB * D_DIM];         // 2 MB fp16 emb * 4096 (filter only)
__device__ float g_wt[D_DIM * D_DIM];         // transposed conv weights
__device__ float g_esq[K_CB];                 // ||e_k||^2 (sequential chain)
__device__ float g_zsq[N_PIX];                // ||z_n||^2 (sequential chain)
__device__ int   g_idx[N_PIX];
__device__ unsigned int g_counts[K_CB];
__device__ float g_loss;
__device__ unsigned short g_cand[N_PIX * CAP];
__device__ int g_ccnt[N_PIX];

__device__ __forceinline__ void cp16(void* dst, const void* src) {
    unsigned d = (unsigned)__cvta_generic_to_shared(dst);
    asm volatile("cp.async.cg.shared.global [%0], [%1], 16;\n" :: "r"(d), "l"(src));
}

// ============================================================
// prep: transpose W, zero counts/loss
// ============================================================
__global__ void prep_kernel(const float* __restrict__ conv_w) {
    int gid = blockIdx.x * 256 + threadIdx.x;
    if (gid < D_DIM * D_DIM) {
        int c = gid >> 8, d = gid & 255;
        g_wt[gid] = conv_w[d * D_DIM + c];
    }
    if (gid < K_CB) g_counts[gid] = 0u;
    if (gid == 0) g_loss = 0.f;
}

// ============================================================
// esq: strict sequential ascending-d chain; also emit fp16
// codebook scaled by 4096 (exact power-of-2) for the filter.
// ============================================================
__global__ void esq_kernel(const float* __restrict__ emb) {
    int k = blockIdx.x * 256 + threadIdx.x;
    if (k >= K_CB) return;
    const float4* er = (const float4*)(emb + (size_t)k * D_DIM);
    __half2* eh2 = (__half2*)(g_eh + (size_t)k * D_DIM);
    float s = 0.f;
    #pragma unroll 8
    for (int i = 0; i < 64; i++) {
        float4 v = er[i];
        s = __fadd_rn(s, __fmul_rn(v.x, v.x));
        s = __fadd_rn(s, __fmul_rn(v.y, v.y));
        s = __fadd_rn(s, __fmul_rn(v.z, v.z));
        s = __fadd_rn(s, __fmul_rn(v.w, v.w));
        eh2[i * 2 + 0] = __floats2half2_rn(v.x * 4096.f, v.y * 4096.f);
        eh2[i * 2 + 1] = __floats2half2_rn(v.z * 4096.f, v.w * 4096.f);
    }
    g_esq[k] = s;
}

// ============================================================
// conv: Eigen-order ascending-c FMA chain, bias last;
// also writes fp16 z copy for the filter.
// ============================================================
__global__ __launch_bounds__(256) void conv_kernel(const float* __restrict__ x,
                                                   const float* __restrict__ conv_b) {
    __shared__ float xs[D_DIM * 32];
    int t = threadIdx.x;
    int n0 = blockIdx.x * 32;
    int b = n0 >> 10, h = (n0 >> 5) & 31;
    const float* xb = x + (size_t)b * (D_DIM * 1024) + h * 32;

    int lane = t & 31, cg = t >> 5;
    #pragma unroll 4
    for (int i = 0; i < 32; i++) {
        int c = cg * 32 + i;
        xs[c * 32 + lane] = xb[c * 1024 + lane];
    }
    __syncthreads();

    int d = t;
    float4 acc[8];
    #pragma unroll
    for (int p = 0; p < 8; p++) acc[p] = make_float4(0.f, 0.f, 0.f, 0.f);
    const float4* xs4 = (const float4*)xs;

    for (int c0 = 0; c0 < D_DIM; c0 += 8) {
        float w[8];
        #pragma unroll
        for (int cc = 0; cc < 8; cc++) w[cc] = g_wt[(c0 + cc) * D_DIM + d];
        #pragma unroll
        for (int p4 = 0; p4 < 8; p4++) {
            #pragma unroll
            for (int cc = 0; cc < 8; cc++) {
                float4 xv = xs4[(c0 + cc) * 8 + p4];
                acc[p4].x = __fmaf_rn(xv.x, w[cc], acc[p4].x);
                acc[p4].y = __fmaf_rn(xv.y, w[cc], acc[p4].y);
                acc[p4].z = __fmaf_rn(xv.z, w[cc], acc[p4].z);
                acc[p4].w = __fmaf_rn(xv.w, w[cc], acc[p4].w);
            }
        }
    }
    float cb = conv_b[d];
    #pragma unroll
    for (int p4 = 0; p4 < 8; p4++) {
        float v0 = __fadd_rn(acc[p4].x, cb);
        float v1 = __fadd_rn(acc[p4].y, cb);
        float v2 = __fadd_rn(acc[p4].z, cb);
        float v3 = __fadd_rn(acc[p4].w, cb);
        g_z[(size_t)(n0 + p4 * 4 + 0) * D_DIM + d] = v0;
        g_z[(size_t)(n0 + p4 * 4 + 1) * D_DIM + d] = v1;
        g_z[(size_t)(n0 + p4 * 4 + 2) * D_DIM + d] = v2;
        g_z[(size_t)(n0 + p4 * 4 + 3) * D_DIM + d] = v3;
        g_zh[(size_t)(n0 + p4 * 4 + 0) * D_DIM + d] = __float2half_rn(v0);
        g_zh[(size_t)(n0 + p4 * 4 + 1) * D_DIM + d] = __float2half_rn(v1);
        g_zh[(size_t)(n0 + p4 * 4 + 2) * D_DIM + d] = __float2half_rn(v2);
        g_zh[(size_t)(n0 + p4 * 4 + 3) * D_DIM + d] = __float2half_rn(v3);
    }
}

// ============================================================
// zsq: strict sequential ascending-d chain
// ============================================================
__global__ void zsq_kernel() {
    int n = blockIdx.x * 256 + threadIdx.x;
    const float4* zr = (const float4*)(g_z + (size_t)n * D_DIM);
    float s = 0.f;
    #pragma unroll 16
    for (int i = 0; i < 64; i++) {
        float4 v = zr[i];
        s = __fadd_rn(s, __fmul_rn(v.x, v.x));
        s = __fadd_rn(s, __fmul_rn(v.y, v.y));
        s = __fadd_rn(s, __fmul_rn(v.z, v.z));
        s = __fadd_rn(s, __fmul_rn(v.w, v.w));
    }
    g_zsq[n] = s;
}

// ============================================================
// dist_mma: fp16 m16n8k16 mma filter; per-pixel shared running
// min + candidate push within MARGIN. CTA = 128 pixels, 32
// code-tiles of 128, E staged 64-dim chunks (2-stage cp.async).
// smem: zA 64KB (A-frag-packed half2) | eB 2x18KB | misc 2KB |
//       cand 16KB  => 118KB, 1 CTA/SM.
// ============================================================
#define EBS_U32 36   // 72 halves per code row
__global__ void __launch_bounds__(256, 1) dist_mma_kernel() {
    extern __shared__ char smem[];
    unsigned* zA   = (unsigned*)smem;                       // 65536 B (16384 u32)
    unsigned* eB   = (unsigned*)(smem + 65536);             // 36864 B
    float* zsq_s = (float*)(smem + 65536 + 36864);          // 512 B
    float* esq_s = zsq_s + 128;
    float* minv  = esq_s + 128;
    int*   cnt_s = (int*)(minv + 128);
    unsigned short* cand_s = (unsigned short*)(cnt_s + 128); // 16384 B

    int t = threadIdx.x;
    int lane = t & 31, warp = t >> 5;
    int wm = warp >> 2, wn = warp & 3;         // 2 x 4 warp grid
    int g = lane >> 2, q = lane & 3;
    int n0 = blockIdx.x * 128;

    if (t < 128) { zsq_s[t] = g_zsq[n0 + t]; minv[t] = 3.0e38f; cnt_s[t] = 0; }

    // stage Z tile: coalesced read of g_zh (half2=u32), scatter into
    // m16n8k16 A-fragment order: zA[(kstep*8+mtile)*128 + lane*4 + comp],
    // comp = hi + 2*khi; value = half2(z[row][2q+8khi+16ks], next dim)
    const unsigned* zh32 = (const unsigned*)g_zh;
    #pragma unroll 8
    for (int l = 0; l < 64; l++) {
        int idx = t + 256 * l;                 // 16384 u32
        int srow = idx >> 7, scol = idx & 127;
        unsigned v = zh32[(size_t)(n0 + srow) * 128 + scol];
        int mtile = srow >> 4, rr = srow & 15, gg = rr & 7, hi = rr >> 3;
        int ks = scol >> 3, rem = scol & 7, khi = rem >> 2, qq = rem & 3;
        zA[(ks * 8 + mtile) * 128 + (gg * 4 + qq) * 4 + (hi + 2 * khi)] = v;
    }

    // prologue: stage 0 (kt=0, kc=0): 128 code rows x 64 dims (128B each)
    {
        const __half* src0 = g_eh;
        #pragma unroll
        for (int l = 0; l < 4; l++) {
            int idx = t + 256 * l;             // 1024 cp16
            int crow = idx >> 3, seg = idx & 7;
            cp16((char*)eB + crow * 144 + seg * 16,
                 src0 + (size_t)crow * 256 + seg * 8);
        }
        asm volatile("cp.async.commit_group;\n");
    }

    float acc[4][4][4];
    float lbest[8];
    #pragma unroll
    for (int i = 0; i < 8; i++) lbest[i] = 3.0e38f;

    #pragma unroll 1
    for (int s = 0; s < 128; s++) {
        int kc = s & 3, buf = s & 1, kt = s >> 2;
        if (s + 1 < 128) {
            int kt1 = (s + 1) >> 2, kc1 = (s + 1) & 3, buf1 = (s + 1) & 1;
            char* dbase = (char*)eB + buf1 * 18432;
            const __half* src0 = g_eh + (size_t)(kt1 * 128) * 256 + kc1 * 64;
            #pragma unroll
            for (int l = 0; l < 4; l++) {
                int idx = t + 256 * l;
                int crow = idx >> 3, seg = idx & 7;
                cp16(dbase + crow * 144 + seg * 16,
                     src0 + (size_t)crow * 256 + seg * 8);
            }
            asm volatile("cp.async.commit_group;\n");
            asm volatile("cp.async.wait_group 1;\n");
        } else {
            asm volatile("cp.async.wait_group 0;\n");
        }
        __syncthreads();

        if (kc == 0) {
            if (t < 128) esq_s[t] = g_esq[kt * 128 + t];
            #pragma unroll
            for (int mi = 0; mi < 4; mi++)
                #pragma unroll
                for (int ni = 0; ni < 4; ni++)
                    #pragma unroll
                    for (int c = 0; c < 4; c++) acc[mi][ni][c] = 0.f;
        }

        unsigned* ebuf = eB + buf * (18432 / 4);
        #pragma unroll
        for (int ks = 0; ks < 4; ks++) {       // 4 k-steps of 16 dims
            int kg = kc * 4 + ks;              // absolute kstep16 (0..15)
            unsigned a[4][4], bfr[4][2];
            #pragma unroll
            for (int mi = 0; mi < 4; mi++) {
                int mtile = wm * 4 + mi;
                uint4 av = ((const uint4*)zA)[(kg * 8 + mtile) * 32 + lane];
                a[mi][0] = av.x; a[mi][1] = av.y; a[mi][2] = av.z; a[mi][3] = av.w;
            }
            #pragma unroll
            for (int ni = 0; ni < 4; ni++) {
                int cl = wn * 32 + ni * 8 + g;
                bfr[ni][0] = ebuf[cl * EBS_U32 + ks * 8 + q];
                bfr[ni][1] = ebuf[cl * EBS_U32 + ks * 8 + q + 4];
            }
            #pragma unroll
            for (int mi = 0; mi < 4; mi++)
                #pragma unroll
                for (int ni = 0; ni < 4; ni++)
                    asm volatile(
                        "mma.sync.aligned.m16n8k16.row.col.f32.f16.f16.f32 "
                        "{%0,%1,%2,%3}, {%4,%5,%6,%7}, {%8,%9}, {%0,%1,%2,%3};"
                        : "+f"(acc[mi][ni][0]), "+f"(acc[mi][ni][1]),
                          "+f"(acc[mi][ni][2]), "+f"(acc[mi][ni][3])
                        : "r"(a[mi][0]), "r"(a[mi][1]), "r"(a[mi][2]), "r"(a[mi][3]),
                          "r"(bfr[ni][0]), "r"(bfr[ni][1]));
        }

        if (kc == 3) {
            #pragma unroll
            for (int mi = 0; mi < 4; mi++) {
                #pragma unroll
                for (int hi = 0; hi < 2; hi++) {
                    int r = wm * 64 + mi * 16 + hi * 8 + g;
                    float zq = zsq_s[r];
                    int slot = mi * 2 + hi;
                    #pragma unroll
                    for (int ni = 0; ni < 4; ni++) {
                        #pragma unroll
                        for (int cc = 0; cc < 2; cc++) {
                            int col = wn * 32 + ni * 8 + 2 * q + cc;
                            float gv = acc[mi][ni][hi * 2 + cc];
                            // descale: acc = 4096 * z.e  =>  -2g = -acc/2048
                            float sv = __fadd_rn(zq, esq_s[col]) - gv * 4.8828125e-4f;
                            if (sv < lbest[slot] + MARGIN) {
                                atomicMin((int*)&minv[r], __float_as_int(sv)); // dist>0
                                float cm = minv[r];
                                if (sv < cm + MARGIN) {
                                    int pos = atomicAdd(&cnt_s[r], 1);
                                    if (pos < CAP)
                                        cand_s[r * CAP + pos] = (unsigned short)(kt * 128 + col);
                                }
                                if (sv < lbest[slot]) lbest[slot] = sv;
                            }
                        }
                    }
                }
            }
        }
        __syncthreads();
    }

    if (t < 128) g_ccnt[n0 + t] = cnt_s[t];
    for (int i = t; i < 128 * CAP; i += 256)
        g_cand[(size_t)n0 * CAP + i] = cand_s[i];
}

// ============================================================
// rescore: EXACT ascending-d FMA chain for candidates only;
// packed-u64 min => lowest-index tie-break. Warp per pixel.
// Overflowed pixels: full exact scan (rare).
// ============================================================
__global__ void __launch_bounds__(256) rescore_kernel(const float* __restrict__ emb) {
    __shared__ float zrow[8][256];
    int t = threadIdx.x, lane = t & 31, w = t >> 5;
    int n = blockIdx.x * 8 + w;

    #pragma unroll
    for (int l = 0; l < 2; l++) {
        int f4 = lane + 32 * l;
        ((float4*)zrow[w])[f4] = ((const float4*)g_z)[(size_t)n * 64 + f4];
    }
    __syncwarp();

    int cnt = g_ccnt[n];
    float zq = g_zsq[n];
    const float4* z4 = (const float4*)zrow[w];
    unsigned long long best = 0xFFFFFFFFFFFFFFFFull;

    int total = (cnt <= CAP) ? cnt : K_CB;
    for (int i = lane; i < total; i += 32) {
        int k = (cnt <= CAP) ? (int)g_cand[(size_t)n * CAP + i] : i;
        float a = 0.f;
        const float4* e4 = (const float4*)(emb + (size_t)k * D_DIM);
        #pragma unroll 8
        for (int d4 = 0; d4 < 64; d4++) {
            float4 ev = e4[d4], zv = z4[d4];
            a = __fmaf_rn(zv.x, ev.x, a);
            a = __fmaf_rn(zv.y, ev.y, a);
            a = __fmaf_rn(zv.z, ev.z, a);
            a = __fmaf_rn(zv.w, ev.w, a);
        }
        float s = __fadd_rn(__fadd_rn(zq, g_esq[k]), -2.f * a);
        unsigned u = __float_as_uint(s);
        u = (u & 0x80000000u) ? ~u : (u | 0x80000000u);
        unsigned long long key = ((unsigned long long)u << 32) | (unsigned)k;
        if (key < best) best = key;
    }
    #pragma unroll
    for (int off = 16; off; off >>= 1) {
        unsigned long long o = __shfl_xor_sync(0xffffffffu, best, off);
        if (o < best) best = o;
    }
    if (lane == 0) g_idx[n] = (int)(best & 0xFFFFFFFFu);
}

// ============================================================
// epilogue: out = fl(z + fl(q - z)); loss partials; histogram
// ============================================================
__global__ __launch_bounds__(256) void epilogue_kernel(const float* __restrict__ emb,
                                                       float* __restrict__ out) {
    __shared__ float st_s[D_DIM * 33];
    __shared__ int idx_s[32];
    __shared__ float wsum[8];
    int t = threadIdx.x;
    int bh = blockIdx.x;
    int b = bh >> 5, h = bh & 31;
    int n0 = bh * 32;

    if (t < 32) idx_s[t] = g_idx[n0 + t];
    __syncthreads();

    float lsum = 0.f;
    for (int p = 0; p < 32; p++) {
        float zv = g_z[(size_t)(n0 + p) * D_DIM + t];
        float qv = emb[(size_t)idx_s[p] * D_DIM + t];
        float diff = __fadd_rn(qv, -zv);
        lsum += diff * diff;
        st_s[t * 33 + p] = __fadd_rn(zv, diff);
    }
    __syncthreads();

    int w = t & 31, dg = t >> 5;
    float* ob = out + (size_t)b * (D_DIM * 1024) + h * 32;
    #pragma unroll 4
    for (int dd = 0; dd < 32; dd++) {
        int d = dg * 32 + dd;
        ob[(size_t)d * 1024 + w] = st_s[d * 33 + w];
    }

    #pragma unroll
    for (int off = 16; off; off >>= 1) lsum += __shfl_xor_sync(0xffffffffu, lsum, off);
    if ((t & 31) == 0) wsum[t >> 5] = lsum;
    __syncthreads();
    if (t == 0) {
        float s = 0.f;
        #pragma unroll
        for (int i = 0; i < 8; i++) s += wsum[i];
        atomicAdd(&g_loss, s);
    }
    if (t < 32) atomicAdd(&g_counts[idx_s[t]], 1u);
}

// ============================================================
// finalize
// ============================================================
__global__ void finalize_kernel(float* __restrict__ out, int out_size) {
    __shared__ float red[512];
    int t = threadIdx.x;
    float s = 0.f;
    for (int k = t; k < K_CB; k += 512) {
        float avg = (float)g_counts[k] / (float)N_PIX;
        s += avg * logf(avg + 1e-10f);
    }
    red[t] = s;
    __syncthreads();
    for (int o = 256; o; o >>= 1) {
        if (t < o) red[t] += red[t + o];
        __syncthreads();
    }
    if (t == 0) {
        out[out_size - 2] = 1.25f * (g_loss / (float)(N_PIX * D_DIM));
        out[out_size - 1] = expf(-red[0]);
    }
}

extern "C" void kernel_launch(void* const* d_in, const int* in_sizes, int n_in,
                              void* d_out, int out_size) {
    const float* x      = (const float*)d_in[0];
    const float* conv_w = (const float*)d_in[1];
    const float* conv_b = (const float*)d_in[2];
    const float* emb    = (const float*)d_in[3];
    float* out = (float*)d_out;

    const int DIST_SMEM = 65536 + 36864 + 4 * 512 + 16384;   // 120832 B
    cudaFuncSetAttribute(dist_mma_kernel,
                         cudaFuncAttributeMaxDynamicSharedMemorySize, DIST_SMEM);

    prep_kernel<<<257, 256>>>(conv_w);
    esq_kernel<<<16, 256>>>(emb);
    conv_kernel<<<N_PIX / 32, 256>>>(x, conv_b);
    zsq_kernel<<<N_PIX / 256, 256>>>();
    dist_mma_kernel<<<N_PIX / 128, 256, DIST_SMEM>>>();
    rescore_kernel<<<N_PIX / 8, 256>>>(emb);
    epilogue_kernel<<<N_PIX / 32, 256>>>(emb, out);
    finalize_kernel<<<1, 512>>>(out, out_size);
}